// round 1
// baseline (speedup 1.0000x reference)
#include <cuda_runtime.h>
#include <cstdint>
#include <math.h>

#define NIMG 16
#define NPROP 16384
#define NGT 128
#define M_TOT (NPROP + NGT)   // 16512
#define KPOS 128
#define KNEG 384
#define NSAMP 512

// ---------------- scratch (no allocations allowed) ----------------
__device__ int g_label[NIMG * M_TOT];
__device__ int g_clamp[NIMG * M_TOT];
__device__ unsigned long long g_key[2][NIMG * M_TOT];
__device__ int g_samp[NIMG * NSAMP];

// ---------------- threefry2x32 (matches jax._src.prng) ----------------
__device__ __forceinline__ uint2 threefry2x32(unsigned k0, unsigned k1,
                                              unsigned x0, unsigned x1) {
    unsigned ks2 = k0 ^ k1 ^ 0x1BD11BDAu;
    x0 += k0; x1 += k1;
#define TF_R(r) { x0 += x1; x1 = (x1 << (r)) | (x1 >> (32 - (r))); x1 ^= x0; }
    TF_R(13) TF_R(15) TF_R(26) TF_R(6)
    x0 += k1; x1 += ks2 + 1u;
    TF_R(17) TF_R(29) TF_R(16) TF_R(24)
    x0 += ks2; x1 += k0 + 2u;
    TF_R(13) TF_R(15) TF_R(26) TF_R(6)
    x0 += k0; x1 += k1 + 3u;
    TF_R(17) TF_R(29) TF_R(16) TF_R(24)
    x0 += k1; x1 += ks2 + 4u;
    TF_R(13) TF_R(15) TF_R(26) TF_R(6)
    x0 += ks2; x1 += k0 + 5u;
#undef TF_R
    return make_uint2(x0, x1);
}

// rscore[i,m] — partitionable threefry path (JAX >= 0.5 default):
// flat counter split into (hi,lo)=(0,f); 32-bit bits = out0 ^ out1.
__device__ __forceinline__ float rscore_at(unsigned f) {
    uint2 o = threefry2x32(0u, 42u, 0u, f);
    unsigned bits = o.x ^ o.y;
    return __uint_as_float((bits >> 9) | 0x3f800000u) - 1.0f;
}

// ---------------- kernel A: match + label + score key ----------------
__global__ void prep_kernel(const float* __restrict__ proposals,
                            const float* __restrict__ gt_boxes,
                            const int* __restrict__ gt_labels) {
    __shared__ float4 s_gt[NGT];
    __shared__ float s_area[NGT];
    __shared__ int s_lab[NGT];
    const int i = blockIdx.y;
    const int t = threadIdx.x;
    const float* gtb = gt_boxes + i * NGT * 4;
    for (int j = t; j < NGT; j += blockDim.x) {
        float x1 = gtb[j*4+0], y1 = gtb[j*4+1], x2 = gtb[j*4+2], y2 = gtb[j*4+3];
        s_gt[j] = make_float4(x1, y1, x2, y2);
        s_area[j] = __fmul_rn(__fsub_rn(x2, x1), __fsub_rn(y2, y1));
        s_lab[j] = gt_labels[i*NGT + j];
    }
    __syncthreads();
    const int m = blockIdx.x * blockDim.x + t;
    if (m >= M_TOT) return;

    float4 p;
    if (m < NPROP) {
        const float* pp = proposals + (size_t)(i*NPROP + m) * 4;
        p = make_float4(pp[0], pp[1], pp[2], pp[3]);
    } else {
        p = s_gt[m - NPROP];
    }
    const float area_b = __fmul_rn(__fsub_rn(p.z, p.x), __fsub_rn(p.w, p.y));

    float best = -1.0f; int arg = 0;
    #pragma unroll 4
    for (int j = 0; j < NGT; j++) {
        float4 g = s_gt[j];
        float lx = fmaxf(g.x, p.x), ly = fmaxf(g.y, p.y);
        float rx = fminf(g.z, p.z), ry = fminf(g.w, p.w);
        float w = fmaxf(__fsub_rn(rx, lx), 0.0f);
        float h = fmaxf(__fsub_rn(ry, ly), 0.0f);
        float inter = __fmul_rn(w, h);
        float denom = __fsub_rn(__fadd_rn(s_area[j], area_b), inter);
        float iou = __fdiv_rn(inter, denom);
        if (iou > best) { best = iou; arg = j; }   // first-max == jnp.argmax
    }
    const bool pos = (best >= 0.5f);
    const int label = pos ? s_lab[arg] : 0;       // FG==BG==0.5 -> no ignore band
    const int clamp = pos ? arg : 0;              // clip(matches,0): negatives -> gt 0

    const float score = rscore_at((unsigned)(i * M_TOT + m));
    // sort key: score desc, ties -> smaller index first (lax.top_k tie rule)
    const unsigned long long key =
        ((unsigned long long)__float_as_uint(score) << 32) | (unsigned)(~(unsigned)m);

    const int gi = i * M_TOT + m;
    g_label[gi] = label;
    g_clamp[gi] = clamp;
    g_key[0][gi] = (label >= 1) ? key : 0ULL;
    g_key[1][gi] = (label == 0) ? key : 0ULL;
}

// ---------------- kernel B: exact top-k (radix select + bitonic) ----------------
__global__ void select_kernel() {
    __shared__ int hist[256];
    __shared__ unsigned long long gath[NSAMP];
    __shared__ int s_cnt;
    __shared__ int s_kk;
    __shared__ unsigned long long s_pref;

    const int i = blockIdx.x;
    const int tid = threadIdx.x;
    const int NT = blockDim.x;

    for (int c = 0; c < 2; c++) {
        const unsigned long long* __restrict__ keys = g_key[c] + (size_t)i * M_TOT;
        const int k = c ? KNEG : KPOS;

        // MSD radix select for the k-th largest (keys are all distinct)
        int kk = k;
        unsigned long long prefix = 0, mask = 0;
        for (int shift = 56; shift >= 0; shift -= 8) {
            for (int b = tid; b < 256; b += NT) hist[b] = 0;
            __syncthreads();
            for (int m = tid; m < M_TOT; m += NT) {
                unsigned long long key = keys[m];
                if ((key & mask) == prefix)
                    atomicAdd(&hist[(int)((key >> shift) & 255ULL)], 1);
            }
            __syncthreads();
            if (tid == 0) {
                int cum = 0, b = 255;
                for (; b > 0; b--) {
                    if (cum + hist[b] >= kk) break;
                    cum += hist[b];
                }
                s_kk = kk - cum;
                s_pref = prefix | ((unsigned long long)b << shift);
            }
            __syncthreads();
            kk = s_kk; prefix = s_pref;
            mask |= (255ULL << shift);
            __syncthreads();
        }
        const unsigned long long T = prefix;   // exact k-th largest key

        if (tid == 0) s_cnt = 0;
        __syncthreads();
        for (int m = tid; m < M_TOT; m += NT) {
            unsigned long long key = keys[m];
            if (key >= T) { int p = atomicAdd(&s_cnt, 1); gath[p] = key; }
        }
        for (int t2 = tid; t2 < NSAMP; t2 += NT) if (t2 >= k) gath[t2] = 0ULL;
        __syncthreads();

        // bitonic sort, descending, 512 elements
        for (int size = 2; size <= NSAMP; size <<= 1) {
            for (int stride = size >> 1; stride > 0; stride >>= 1) {
                if (tid < NSAMP) {
                    int t2 = tid, partner = t2 ^ stride;
                    if (partner > t2) {
                        bool desc = ((t2 & size) == 0);
                        unsigned long long a = gath[t2], b = gath[partner];
                        bool sw = desc ? (a < b) : (a > b);
                        if (sw) { gath[t2] = b; gath[partner] = a; }
                    }
                }
                __syncthreads();
            }
        }

        const int base = i * NSAMP + (c ? KPOS : 0);
        if (tid < k)
            g_samp[base + tid] = (int)(~(unsigned)(gath[tid] & 0xFFFFFFFFULL));
        __syncthreads();
    }
}

// ---------------- kernel C: gather + encode + write ----------------
__global__ void out_kernel(const float* __restrict__ proposals,
                           const float* __restrict__ gt_boxes,
                           float* __restrict__ out) {
    const int i = blockIdx.x;
    const int s = threadIdx.x;          // 512 threads
    const int m = g_samp[i * NSAMP + s];
    const int gi = i * M_TOT + m;
    const int label = g_label[gi];
    const int cl = g_clamp[gi];

    float4 p;
    if (m < NPROP) {
        const float* pp = proposals + (size_t)(i*NPROP + m) * 4;
        p = make_float4(pp[0], pp[1], pp[2], pp[3]);
    } else {
        const float* pp = gt_boxes + (size_t)(i*NGT + (m - NPROP)) * 4;
        p = make_float4(pp[0], pp[1], pp[2], pp[3]);
    }
    const float* g = gt_boxes + (size_t)(i*NGT + cl) * 4;

    float rw = p.z - p.x, rh = p.w - p.y;
    float rcx = p.x + 0.5f * rw, rcy = p.y + 0.5f * rh;
    float gw = g[2] - g[0], gh = g[3] - g[1];
    float gcx = g[0] + 0.5f * gw, gcy = g[1] + 0.5f * gh;

    float t0 = 10.0f * __fdiv_rn(gcx - rcx, rw);
    float t1 = 10.0f * __fdiv_rn(gcy - rcy, rh);
    float t2 = 5.0f * logf(__fdiv_rn(gw, rw));
    float t3 = 5.0f * logf(__fdiv_rn(gh, rh));

    const int o = (i * NSAMP + s) * 4;
    out[o + 0] = t0; out[o + 1] = t1; out[o + 2] = t2; out[o + 3] = t3;
    out[NIMG*NSAMP*4 + i*NSAMP + s] = (float)label;
    out[NIMG*NSAMP*4 + NIMG*NSAMP + i*NSAMP + s] = (float)m;
}

// ---------------- launch ----------------
extern "C" void kernel_launch(void* const* d_in, const int* in_sizes, int n_in,
                              void* d_out, int out_size) {
    const float* proposals = (const float*)d_in[0];
    const float* gt_boxes  = (const float*)d_in[1];
    const int*   gt_labels = (const int*)d_in[2];
    float* out = (float*)d_out;

    prep_kernel<<<dim3((M_TOT + 255) / 256, NIMG), 256>>>(proposals, gt_boxes, gt_labels);
    select_kernel<<<NIMG, 1024>>>();
    out_kernel<<<NIMG, NSAMP>>>(proposals, gt_boxes, out);
}

// round 3
// speedup vs baseline: 2.6376x; 2.6376x over previous
#include <cuda_runtime.h>
#include <cstdint>
#include <math.h>

#define NIMG 16
#define NPROP 16384
#define NGT 128
#define M_TOT (NPROP + NGT)   // 16512
#define KPOS 128
#define KNEG 384
#define NSAMP 512
#define NCAND 512

// ---------------- scratch ----------------
__device__ unsigned g_rec[NIMG * M_TOT];    // (score_bits<<1) | is_pos
__device__ int g_labcl[NIMG * M_TOT];       // label | (clamped_gt << 8)

// ---------------- threefry2x32 (jax partitionable path) ----------------
__device__ __forceinline__ unsigned rscore_bits(unsigned f) {
    unsigned k0 = 0u, k1 = 42u;
    unsigned ks2 = k0 ^ k1 ^ 0x1BD11BDAu;
    unsigned x0 = 0u, x1 = f;
    x0 += k0; x1 += k1;
#define TF_R(r) { x0 += x1; x1 = (x1 << (r)) | (x1 >> (32 - (r))); x1 ^= x0; }
    TF_R(13) TF_R(15) TF_R(26) TF_R(6)
    x0 += k1; x1 += ks2 + 1u;
    TF_R(17) TF_R(29) TF_R(16) TF_R(24)
    x0 += ks2; x1 += k0 + 2u;
    TF_R(13) TF_R(15) TF_R(26) TF_R(6)
    x0 += k0; x1 += k1 + 3u;
    TF_R(17) TF_R(29) TF_R(16) TF_R(24)
    x0 += k1; x1 += ks2 + 4u;
    TF_R(13) TF_R(15) TF_R(26) TF_R(6)
    x0 += ks2; x1 += k0 + 5u;
#undef TF_R
    unsigned bits = x0 ^ x1;
    float s = __uint_as_float((bits >> 9) | 0x3f800000u) - 1.0f;
    return __float_as_uint(s);   // in [0, 0x3F7FFFFF]
}

// exact real comparison: inter/den > bi/bd  (operands >= 0, den,bd > 0)
__device__ __forceinline__ bool q_gt(float inter, float den, float bi, float bd) {
    float u = __fmul_rn(inter, bd);
    float v = __fmul_rn(bi, den);
    float eu = __fmaf_rn(inter, bd, -u);   // exact residual
    float ev = __fmaf_rn(bi, den, -v);
    return (u > v) || (u == v && eu > ev);
}

// ---------------- kernel A: match + label + record ----------------
__global__ void __launch_bounds__(256) prep_kernel(
        const float4* __restrict__ proposals,
        const float4* __restrict__ gt_boxes,
        const int* __restrict__ gt_labels) {
    __shared__ float4 s_gt[NGT];
    __shared__ float  s_area[NGT];
    __shared__ int    s_lab[NGT];
    const int i = blockIdx.y;
    const int t = threadIdx.x;
    if (t < NGT) {
        float4 g = gt_boxes[i * NGT + t];
        s_gt[t] = g;
        s_area[t] = __fmul_rn(__fsub_rn(g.z, g.x), __fsub_rn(g.w, g.y));
        s_lab[t] = gt_labels[i * NGT + t];
    }
    __syncthreads();

    const int idx = blockIdx.x * 256 + t;
    const int m0 = 2 * idx, m1 = m0 + 1;
    if (m0 >= M_TOT) return;

    float4 p0 = (m0 < NPROP) ? proposals[(size_t)i * NPROP + m0] : s_gt[m0 - NPROP];
    float4 p1 = (m1 < NPROP) ? proposals[(size_t)i * NPROP + m1] : s_gt[m1 - NPROP];
    const float ab0 = __fmul_rn(__fsub_rn(p0.z, p0.x), __fsub_rn(p0.w, p0.y));
    const float ab1 = __fmul_rn(__fsub_rn(p1.z, p1.x), __fsub_rn(p1.w, p1.y));

    float bi0 = 0.0f, bd0 = 1.0f, bi1 = 0.0f, bd1 = 1.0f;
    int a0 = 0, a1 = 0;

    #pragma unroll 8
    for (int j = 0; j < NGT; j++) {
        float4 g = s_gt[j];
        float sa = s_area[j];
        {
            float w = fmaxf(__fsub_rn(fminf(g.z, p0.z), fmaxf(g.x, p0.x)), 0.0f);
            float h = fmaxf(__fsub_rn(fminf(g.w, p0.w), fmaxf(g.y, p0.y)), 0.0f);
            float inter = __fmul_rn(w, h);
            float den = __fsub_rn(__fadd_rn(sa, ab0), inter);
            if (q_gt(inter, den, bi0, bd0)) { bi0 = inter; bd0 = den; a0 = j; }
        }
        {
            float w = fmaxf(__fsub_rn(fminf(g.z, p1.z), fmaxf(g.x, p1.x)), 0.0f);
            float h = fmaxf(__fsub_rn(fminf(g.w, p1.w), fmaxf(g.y, p1.y)), 0.0f);
            float inter = __fmul_rn(w, h);
            float den = __fsub_rn(__fadd_rn(sa, ab1), inter);
            if (q_gt(inter, den, bi1, bd1)) { bi1 = inter; bd1 = den; a1 = j; }
        }
    }

    bool pos0 = __fdiv_rn(bi0, bd0) >= 0.5f;
    bool pos1 = __fdiv_rn(bi1, bd1) >= 0.5f;

    int lab0 = pos0 ? s_lab[a0] : 0;
    int lab1 = pos1 ? s_lab[a1] : 0;
    int cl0  = pos0 ? a0 : 0;
    int cl1  = pos1 ? a1 : 0;

    unsigned sb0 = rscore_bits((unsigned)(i * M_TOT + m0));
    unsigned sb1 = rscore_bits((unsigned)(i * M_TOT + m1));

    const int gi = i * M_TOT;
    g_labcl[gi + m0] = lab0 | (cl0 << 8);
    g_labcl[gi + m1] = lab1 | (cl1 << 8);
    g_rec[gi + m0] = (sb0 << 1) | (pos0 ? 1u : 0u);
    g_rec[gi + m1] = (sb1 << 1) | (pos1 ? 1u : 0u);
}

// ---------------- kernel B: 2-level histogram top-k + sort + encode ----------------
__global__ void __launch_bounds__(1024) select_kernel(
        const float4* __restrict__ proposals,
        const float4* __restrict__ gt_boxes,
        float* __restrict__ out) {
    __shared__ int hist[8192];
    __shared__ int csum[1024];
    __shared__ int c2[32];
    __shared__ unsigned long long cand[NCAND];
    __shared__ int s_cnt, s_B, s_kk, s_B2;

    const int i = blockIdx.x;
    const int cat = blockIdx.y;            // 0 = pos, 1 = neg
    const unsigned want = cat ? 0u : 1u;
    const int k = cat ? KNEG : KPOS;
    const int t = threadIdx.x;
    const unsigned* __restrict__ rec = g_rec + (size_t)i * M_TOT;

    // ---- level 1: histogram over top 13 bits (r>>18 < 8128) ----
    for (int b = t; b < 8192; b += 1024) hist[b] = 0;
    if (t < NCAND) cand[t] = 0ULL;
    if (t == 0) s_cnt = 0;
    __syncthreads();

    for (int m = t; m < M_TOT; m += 1024) {
        unsigned r = rec[m];
        if ((r & 1u) == want) atomicAdd(&hist[r >> 18], 1);
    }
    __syncthreads();

    {
        int s = 0;
        #pragma unroll
        for (int b = 0; b < 8; b++) s += hist[t * 8 + b];
        csum[t] = s;
    }
    __syncthreads();
    if (t < 32) {
        int s = 0;
        #pragma unroll
        for (int b = 0; b < 32; b++) s += csum[t * 32 + b];
        c2[t] = s;
    }
    __syncthreads();
    if (t == 0) {
        int acc = 0;
        int cc = 31;
        for (; cc > 0; cc--) { if (acc + c2[cc] >= k) break; acc += c2[cc]; }
        int tt = cc * 32 + 31;
        for (; tt > cc * 32; tt--) { if (acc + csum[tt] >= k) break; acc += csum[tt]; }
        int b = tt * 8 + 7;
        for (; b > tt * 8; b--) { if (acc + hist[b] >= k) break; acc += hist[b]; }
        s_B = b;
        s_kk = k - acc;          // items still needed from bucket B
    }
    __syncthreads();
    const unsigned B = (unsigned)s_B;
    const int kk = s_kk;
    __syncthreads();

    // ---- level 2: refine within bucket B over bits [5,18) ----
    for (int b = t; b < 8192; b += 1024) hist[b] = 0;
    __syncthreads();
    for (int m = t; m < M_TOT; m += 1024) {
        unsigned r = rec[m];
        if ((r & 1u) == want && (r >> 18) == B)
            atomicAdd(&hist[(r >> 5) & 0x1FFFu], 1);
    }
    __syncthreads();
    {
        int s = 0;
        #pragma unroll
        for (int b = 0; b < 8; b++) s += hist[t * 8 + b];
        csum[t] = s;
    }
    __syncthreads();
    if (t < 32) {
        int s = 0;
        #pragma unroll
        for (int b = 0; b < 32; b++) s += csum[t * 32 + b];
        c2[t] = s;
    }
    __syncthreads();
    if (t == 0) {
        int acc = 0;
        int cc = 31;
        for (; cc > 0; cc--) { if (acc + c2[cc] >= kk) break; acc += c2[cc]; }
        int tt = cc * 32 + 31;
        for (; tt > cc * 32; tt--) { if (acc + csum[tt] >= kk) break; acc += csum[tt]; }
        int b = tt * 8 + 7;
        for (; b > tt * 8; b--) { if (acc + hist[b] >= kk) break; acc += hist[b]; }
        s_B2 = b;
    }
    __syncthreads();
    const unsigned T = (B << 18) | ((unsigned)s_B2 << 5);

    // ---- gather candidates (count in [k, k + granule ties], << NCAND) ----
    for (int m = t; m < M_TOT; m += 1024) {
        unsigned r = rec[m];
        if ((r & 1u) == want && r >= T) {
            int p = atomicAdd(&s_cnt, 1);
            if (p < NCAND)
                cand[p] = ((unsigned long long)(r >> 1) << 32) | (unsigned)(~(unsigned)m);
        }
    }
    __syncthreads();

    // ---- bitonic sort, descending, NCAND=512 elements ----
    for (int size = 2; size <= NCAND; size <<= 1) {
        for (int stride = size >> 1; stride > 0; stride >>= 1) {
            if (t < NCAND) {
                int partner = t ^ stride;
                if (partner > t) {
                    bool desc = ((t & size) == 0);
                    unsigned long long a = cand[t], b = cand[partner];
                    if (desc ? (a < b) : (a > b)) { cand[t] = b; cand[partner] = a; }
                }
            }
            __syncthreads();
        }
    }

    // ---- epilogue: gather + encode + write ----
    if (t < k) {
        unsigned long long key = cand[t];
        int m = (int)(~(unsigned)(key & 0xFFFFFFFFULL));
        int labcl = g_labcl[(size_t)i * M_TOT + m];
        int label = labcl & 0xFF;
        int cl = labcl >> 8;

        float4 p = (m < NPROP) ? proposals[(size_t)i * NPROP + m]
                               : gt_boxes[i * NGT + (m - NPROP)];
        float4 g = gt_boxes[i * NGT + cl];

        float rw = p.z - p.x, rh = p.w - p.y;
        float rcx = p.x + 0.5f * rw, rcy = p.y + 0.5f * rh;
        float gw = g.z - g.x, gh = g.w - g.y;
        float gcx = g.x + 0.5f * gw, gcy = g.y + 0.5f * gh;

        float t0 = 10.0f * __fdiv_rn(gcx - rcx, rw);
        float t1 = 10.0f * __fdiv_rn(gcy - rcy, rh);
        float t2 = 5.0f * logf(__fdiv_rn(gw, rw));
        float t3 = 5.0f * logf(__fdiv_rn(gh, rh));

        int row = i * NSAMP + (cat ? KPOS : 0) + t;
        out[row * 4 + 0] = t0;
        out[row * 4 + 1] = t1;
        out[row * 4 + 2] = t2;
        out[row * 4 + 3] = t3;
        out[NIMG * NSAMP * 4 + row] = (float)label;
        out[NIMG * NSAMP * 4 + NIMG * NSAMP + row] = (float)m;
    }
}

// ---------------- launch ----------------
extern "C" void kernel_launch(void* const* d_in, const int* in_sizes, int n_in,
                              void* d_out, int out_size) {
    const float4* proposals = (const float4*)d_in[0];
    const float4* gt_boxes  = (const float4*)d_in[1];
    const int*    gt_labels = (const int*)d_in[2];
    float* out = (float*)d_out;

    prep_kernel<<<dim3((M_TOT / 2 + 255) / 256, NIMG), 256>>>(proposals, gt_boxes, gt_labels);
    select_kernel<<<dim3(NIMG, 2), 1024>>>(proposals, gt_boxes, out);
}

// round 4
// speedup vs baseline: 2.8985x; 1.0989x over previous
#include <cuda_runtime.h>
#include <cstdint>
#include <math.h>

#define NIMG 16
#define NPROP 16384
#define NGT 128
#define M_TOT (NPROP + NGT)   // 16512
#define KPOS 128
#define KNEG 384
#define NSAMP 512
#define NCAND 512

// ---------------- scratch ----------------
__device__ unsigned g_rec[NIMG * M_TOT];    // (u23 << 1) | is_pos
__device__ int g_labcl[NIMG * M_TOT];       // label | (clamped_gt << 8)  (positives only)

// ---------------- threefry2x32 (jax partitionable path) ----------------
// returns u = bits >> 9 (23-bit uniform); score = u * 2^-23 exactly (monotone)
__device__ __forceinline__ unsigned rscore_u(unsigned f) {
    unsigned k0 = 0u, k1 = 42u;
    unsigned ks2 = k0 ^ k1 ^ 0x1BD11BDAu;
    unsigned x0 = 0u, x1 = f;
    x0 += k0; x1 += k1;
#define TF_R(r) { x0 += x1; x1 = (x1 << (r)) | (x1 >> (32 - (r))); x1 ^= x0; }
    TF_R(13) TF_R(15) TF_R(26) TF_R(6)
    x0 += k1; x1 += ks2 + 1u;
    TF_R(17) TF_R(29) TF_R(16) TF_R(24)
    x0 += ks2; x1 += k0 + 2u;
    TF_R(13) TF_R(15) TF_R(26) TF_R(6)
    x0 += k0; x1 += k1 + 3u;
    TF_R(17) TF_R(29) TF_R(16) TF_R(24)
    x0 += k1; x1 += ks2 + 4u;
    TF_R(13) TF_R(15) TF_R(26) TF_R(6)
    x0 += ks2; x1 += k0 + 5u;
#undef TF_R
    return (x0 ^ x1) >> 9;
}

// ---------------- kernel A: approx match + rare exact redo ----------------
__global__ void __launch_bounds__(256) prep_kernel(
        const float4* __restrict__ proposals,
        const float4* __restrict__ gt_boxes,
        const int* __restrict__ gt_labels) {
    __shared__ float4 s_gt[NGT];
    __shared__ float  s_area[NGT];
    __shared__ int    s_lab[NGT];
    __shared__ int    s_flag[512];
    __shared__ int    s_nflag;

    const int i = blockIdx.y;
    const int t = threadIdx.x;
    if (t == 0) s_nflag = 0;
    if (t < NGT) {
        float4 g = gt_boxes[i * NGT + t];
        s_gt[t] = g;
        s_area[t] = __fmul_rn(__fsub_rn(g.z, g.x), __fsub_rn(g.w, g.y));
        s_lab[t] = gt_labels[i * NGT + t];
    }
    __syncthreads();

    const int m0 = blockIdx.x * 512 + 2 * t;    // block owns 512 consecutive m
    const int gi = i * M_TOT;

    if (m0 < M_TOT) {
        const int m1 = m0 + 1;
        float4 p0 = (m0 < NPROP) ? proposals[(size_t)i * NPROP + m0] : s_gt[m0 - NPROP];
        float4 p1 = (m1 < NPROP) ? proposals[(size_t)i * NPROP + m1] : s_gt[m1 - NPROP];
        const float ab0 = __fmul_rn(__fsub_rn(p0.z, p0.x), __fsub_rn(p0.w, p0.y));
        const float ab1 = __fmul_rn(__fsub_rn(p1.z, p1.x), __fsub_rn(p1.w, p1.y));

        float bi0 = 0.0f, bd0 = 1.0f, bi1 = 0.0f, bd1 = 1.0f;

        #pragma unroll 8
        for (int j = 0; j < NGT; j++) {
            float4 g = s_gt[j];
            float sa = s_area[j];
            {
                float wx = __fsub_rn(fminf(g.z, p0.z), fmaxf(g.x, p0.x));
                float hy = __fsub_rn(fminf(g.w, p0.w), fmaxf(g.y, p0.y));
                float inter = __fmul_rn(fmaxf(wx, 0.0f), fmaxf(hy, 0.0f));
                float den = __fsub_rn(__fadd_rn(sa, ab0), inter);
                float u = __fmul_rn(inter, bd0);
                float d = __fmaf_rn(bi0, den, -u);       // sign of bi0*den - inter*bd0
                if (d < 0.0f) { bi0 = inter; bd0 = den; }
            }
            {
                float wx = __fsub_rn(fminf(g.z, p1.z), fmaxf(g.x, p1.x));
                float hy = __fsub_rn(fminf(g.w, p1.w), fmaxf(g.y, p1.y));
                float inter = __fmul_rn(fmaxf(wx, 0.0f), fmaxf(hy, 0.0f));
                float den = __fsub_rn(__fadd_rn(sa, ab1), inter);
                float u = __fmul_rn(inter, bd1);
                float d = __fmaf_rn(bi1, den, -u);
                if (d < 0.0f) { bi1 = inter; bd1 = den; }
            }
        }

        float q0 = __fdiv_rn(bi0, bd0);
        float q1 = __fdiv_rn(bi1, bd1);
        bool f0 = q0 >= 0.4995f;
        bool f1 = q1 >= 0.4995f;

        // default: negative (pos bit 0); flagged overwritten by redo phase
        uint2 rec2;
        rec2.x = rscore_u((unsigned)(gi + m0)) << 1;
        rec2.y = rscore_u((unsigned)(gi + m1)) << 1;
        *reinterpret_cast<uint2*>(&g_rec[gi + m0]) = rec2;

        if (f0) { int p = atomicAdd(&s_nflag, 1); s_flag[p] = m0; }
        if (f1) { int p = atomicAdd(&s_nflag, 1); s_flag[p] = m1; }
    }
    __syncthreads();

    // ---- exact redo for flagged proposals: one warp per proposal ----
    const int nf = s_nflag;
    const int wid = t >> 5, lane = t & 31;
    for (int e = wid; e < nf; e += 8) {
        const int m = s_flag[e];
        float4 p = (m < NPROP) ? proposals[(size_t)i * NPROP + m] : s_gt[m - NPROP];
        const float ab = __fmul_rn(__fsub_rn(p.z, p.x), __fsub_rn(p.w, p.y));

        // lane j0 = lane, then +32,+64,+96; sequential strict-greater keeps smallest j
        float bi, bd; int bj;
        {
            float4 g = s_gt[lane];
            float wx = __fsub_rn(fminf(g.z, p.z), fmaxf(g.x, p.x));
            float hy = __fsub_rn(fminf(g.w, p.w), fmaxf(g.y, p.y));
            bi = __fmul_rn(fmaxf(wx, 0.0f), fmaxf(hy, 0.0f));
            bd = __fsub_rn(__fadd_rn(s_area[lane], ab), bi);
            bj = lane;
        }
        #pragma unroll
        for (int kk = 1; kk < 4; kk++) {
            int j = lane + kk * 32;
            float4 g = s_gt[j];
            float wx = __fsub_rn(fminf(g.z, p.z), fmaxf(g.x, p.x));
            float hy = __fsub_rn(fminf(g.w, p.w), fmaxf(g.y, p.y));
            float inter = __fmul_rn(fmaxf(wx, 0.0f), fmaxf(hy, 0.0f));
            float den = __fsub_rn(__fadd_rn(s_area[j], ab), inter);
            // exact: inter/den > bi/bd ?
            float u = __fmul_rn(inter, bd), v = __fmul_rn(bi, den);
            float eu = __fmaf_rn(inter, bd, -u), ev = __fmaf_rn(bi, den, -v);
            if ((u > v) || (u == v && eu > ev)) { bi = inter; bd = den; bj = j; }
        }
        // butterfly all-reduce: exact compare, ties -> smaller j
        #pragma unroll
        for (int off = 16; off > 0; off >>= 1) {
            float obi = __shfl_xor_sync(0xFFFFFFFFu, bi, off);
            float obd = __shfl_xor_sync(0xFFFFFFFFu, bd, off);
            int   obj = __shfl_xor_sync(0xFFFFFFFFu, bj, off);
            float u = __fmul_rn(obi, bd), v = __fmul_rn(bi, obd);
            float eu = __fmaf_rn(obi, bd, -u), ev = __fmaf_rn(bi, obd, -v);
            bool gt = (u > v) || (u == v && eu > ev);
            bool eq = (u == v) && (eu == ev);
            if (gt || (eq && obj < bj)) { bi = obi; bd = obd; bj = obj; }
        }
        if (lane == 0) {
            bool pos = __fdiv_rn(bi, bd) >= 0.5f;     // bit-exact threshold
            int label = pos ? s_lab[bj] : 0;
            int cl = pos ? bj : 0;
            g_labcl[gi + m] = label | (cl << 8);
            g_rec[gi + m] = (rscore_u((unsigned)(gi + m)) << 1) | (pos ? 1u : 0u);
        }
    }
}

// ---------------- kernel B: 1-pass histogram top-k + rank sort + encode ----------------
__global__ void __launch_bounds__(1024) select_kernel(
        const float4* __restrict__ proposals,
        const float4* __restrict__ gt_boxes,
        float* __restrict__ out) {
    __shared__ int hist[4096];
    __shared__ int csum[1024];
    __shared__ int c2[32];
    __shared__ unsigned long long cand[NCAND];
    __shared__ int s_cnt, s_B;

    const int i = blockIdx.x;
    const int cat = blockIdx.y;            // 0 = pos, 1 = neg
    const unsigned want = cat ? 0u : 1u;
    const int k = cat ? KNEG : KPOS;
    const int t = threadIdx.x;
    const unsigned* __restrict__ rec = g_rec + (size_t)i * M_TOT;

    #pragma unroll
    for (int b = 0; b < 4; b++) hist[t + b * 1024] = 0;
    if (t == 0) s_cnt = 0;
    __syncthreads();

    // histogram over top 12 bits of u (uniform -> ~4 per bucket)
    for (int m = t; m < M_TOT; m += 1024) {
        unsigned r = rec[m];
        if ((r & 1u) == want) atomicAdd(&hist[r >> 12], 1);
    }
    __syncthreads();

    {
        int s = hist[t * 4] + hist[t * 4 + 1] + hist[t * 4 + 2] + hist[t * 4 + 3];
        csum[t] = s;
    }
    __syncthreads();
    if (t < 32) {
        int s = 0;
        #pragma unroll
        for (int b = 0; b < 32; b++) s += csum[t * 32 + b];
        c2[t] = s;
    }
    __syncthreads();
    if (t == 0) {
        int acc = 0;
        int cc = 31;
        for (; cc > 0; cc--) { if (acc + c2[cc] >= k) break; acc += c2[cc]; }
        int tt = cc * 32 + 31;
        for (; tt > cc * 32; tt--) { if (acc + csum[tt] >= k) break; acc += csum[tt]; }
        int b = tt * 4 + 3;
        for (; b > tt * 4; b--) { if (acc + hist[b] >= k) break; acc += hist[b]; }
        s_B = b;
    }
    __syncthreads();
    const unsigned T = (unsigned)s_B << 12;   // bucket-granular threshold

    // gather: count in [k, k + |bucket B|] << NCAND
    for (int m = t; m < M_TOT; m += 1024) {
        unsigned r = rec[m];
        if ((r & 1u) == want && r >= T) {
            int p = atomicAdd(&s_cnt, 1);
            if (p < NCAND)
                cand[p] = ((unsigned long long)(r >> 1) << 32) | (unsigned)(~(unsigned)m);
        }
    }
    __syncthreads();

    const int C = min(s_cnt, NCAND);

    // rank-counting sort (keys distinct) + fused encode
    if (t < C) {
        const unsigned long long mykey = cand[t];
        int r = 0;
        for (int c = 0; c < C; c++) r += (cand[c] > mykey);

        if (r < k) {
            int m = (int)(~(unsigned)(mykey & 0xFFFFFFFFULL));
            int label = 0, cl = 0;
            if (cat == 0) {
                int labcl = g_labcl[(size_t)i * M_TOT + m];
                label = labcl & 0xFF;
                cl = labcl >> 8;
            }
            float4 p = (m < NPROP) ? proposals[(size_t)i * NPROP + m]
                                   : gt_boxes[i * NGT + (m - NPROP)];
            float4 g = gt_boxes[i * NGT + cl];

            float rw = p.z - p.x, rh = p.w - p.y;
            float rcx = p.x + 0.5f * rw, rcy = p.y + 0.5f * rh;
            float gw = g.z - g.x, gh = g.w - g.y;
            float gcx = g.x + 0.5f * gw, gcy = g.y + 0.5f * gh;

            float t0 = 10.0f * __fdiv_rn(gcx - rcx, rw);
            float t1 = 10.0f * __fdiv_rn(gcy - rcy, rh);
            float t2 = 5.0f * logf(__fdiv_rn(gw, rw));
            float t3 = 5.0f * logf(__fdiv_rn(gh, rh));

            int row = i * NSAMP + (cat ? KPOS : 0) + r;
            out[row * 4 + 0] = t0;
            out[row * 4 + 1] = t1;
            out[row * 4 + 2] = t2;
            out[row * 4 + 3] = t3;
            out[NIMG * NSAMP * 4 + row] = (float)label;
            out[NIMG * NSAMP * 4 + NIMG * NSAMP + row] = (float)m;
        }
    }
}

// ---------------- launch ----------------
extern "C" void kernel_launch(void* const* d_in, const int* in_sizes, int n_in,
                              void* d_out, int out_size) {
    const float4* proposals = (const float4*)d_in[0];
    const float4* gt_boxes  = (const float4*)d_in[1];
    const int*    gt_labels = (const int*)d_in[2];
    float* out = (float*)d_out;

    prep_kernel<<<dim3((M_TOT + 511) / 512, NIMG), 256>>>(proposals, gt_boxes, gt_labels);
    select_kernel<<<dim3(NIMG, 2), 1024>>>(proposals, gt_boxes, out);
}